// round 1
// baseline (speedup 1.0000x reference)
#include <cuda_runtime.h>
#include <cuda_bf16.h>
#include <math.h>

// ---------------- problem constants ----------------
#define BB 2
#define LL 4096
#define DM 256
#define DIN 1024          // D_INNER
#define GN_ 128           // NGROUPS*D_STATE
#define HH 8              // NHEADS
#define PP 128            // HEADDIM
#define DPROJ 2312        // D_IN_PROJ
#define DCONVCH 1280      // D_INNER + 2*GN
#define ROWS (BB*LL)      // 8192
#define EPS_ 1e-5f

#define NPART 8
#define NPN 16            // n per partition
#define SS 4              // scan superstep

// ---------------- scratch (static device allocations) ----------------
__device__ float g_xn[(size_t)ROWS * DM];          // 8 MB
__device__ float g_zx[(size_t)ROWS * DPROJ];       // 75.8 MB
__device__ float g_xconv[(size_t)ROWS * DCONVCH];  // 41.9 MB
__device__ float g_dtpos[(size_t)ROWS * HH];
__device__ float g_dA[(size_t)ROWS * HH];
__device__ float g_xsh[(size_t)ROWS * PP];         // 4.2 MB
__device__ float g_ypart[(size_t)NPART * ROWS * DIN]; // 256 MB
__device__ float g_yg[(size_t)ROWS * DIN];         // 33.5 MB

// ---------------- helpers ----------------
__device__ __forceinline__ float siluf(float x) { return x / (1.f + expf(-x)); }

typedef unsigned long long ull;
__device__ __forceinline__ ull f32x2_fma(ull a, ull b, ull c) {
    ull d; asm("fma.rn.f32x2 %0, %1, %2, %3;" : "=l"(d) : "l"(a), "l"(b), "l"(c)); return d;
}
__device__ __forceinline__ ull f32x2_mul(ull a, ull b) {
    ull d; asm("mul.rn.f32x2 %0, %1, %2;" : "=l"(d) : "l"(a), "l"(b)); return d;
}
__device__ __forceinline__ ull f32x2_pack(float lo, float hi) {
    ull d; asm("mov.b64 %0, {%1, %2};" : "=l"(d) : "f"(lo), "f"(hi)); return d;
}
__device__ __forceinline__ float2 f32x2_unpack(ull v) {
    float2 r; asm("mov.b64 {%0, %1}, %2;" : "=f"(r.x), "=f"(r.y) : "l"(v)); return r;
}

// ---------------- 1) LayerNorm ----------------
__global__ void ln_kernel(const float* __restrict__ u,
                          const float* __restrict__ gamma,
                          const float* __restrict__ beta) {
    __shared__ float red[256];
    const int row = blockIdx.x, tid = threadIdx.x;
    float v = u[(size_t)row * DM + tid];
    red[tid] = v; __syncthreads();
    #pragma unroll
    for (int s = 128; s > 0; s >>= 1) { if (tid < s) red[tid] += red[tid + s]; __syncthreads(); }
    float mu = red[0] * (1.f / 256.f);
    __syncthreads();
    float d = v - mu;
    red[tid] = d * d; __syncthreads();
    #pragma unroll
    for (int s = 128; s > 0; s >>= 1) { if (tid < s) red[tid] += red[tid + s]; __syncthreads(); }
    float var = red[0] * (1.f / 256.f);
    g_xn[(size_t)row * DM + tid] = d * rsqrtf(var + EPS_) * gamma[tid] + beta[tid];
}

// ---------------- 2) SGEMM (fp32, 128x128x16, 8x8 per thread) ----------------
template <int BM, int BN, int BK, int TM, int TN>
__global__ void __launch_bounds__((BM/TM)*(BN/TN))
sgemm_kernel(int M, int N, int K,
             const float* __restrict__ A,
             const float* __restrict__ B,
             const float* __restrict__ Cadd,
             float* __restrict__ C) {
    constexpr int NT = (BM/TM)*(BN/TN);
    __shared__ float As[BK][BM];
    __shared__ float Bs[BK][BN + 4];

    const int tid = threadIdx.x;
    const int tileRow = blockIdx.y * BM;
    const int tileCol = blockIdx.x * BN;
    const int trow = (tid / (BN/TN)) * TM;
    const int tcol = (tid % (BN/TN)) * TN;

    const int aRow0 = tid / (BK/4);
    const int aCol  = (tid % (BK/4)) * 4;
    constexpr int aRowStride = NT / (BK/4);
    const int bRow0 = tid / (BN/4);
    const int bCol  = (tid % (BN/4)) * 4;
    constexpr int bRowStride = NT / (BN/4);

    float acc[TM][TN];
    #pragma unroll
    for (int i = 0; i < TM; ++i)
        #pragma unroll
        for (int j = 0; j < TN; ++j) acc[i][j] = 0.f;

    for (int k0 = 0; k0 < K; k0 += BK) {
        #pragma unroll
        for (int r = aRow0; r < BM; r += aRowStride) {
            float4 v = *(const float4*)(A + (size_t)(tileRow + r) * K + k0 + aCol);
            As[aCol + 0][r] = v.x; As[aCol + 1][r] = v.y;
            As[aCol + 2][r] = v.z; As[aCol + 3][r] = v.w;
        }
        #pragma unroll
        for (int r = bRow0; r < BK; r += bRowStride) {
            const int gc = tileCol + bCol;
            float4 v;
            if (gc + 3 < N) {
                v = *(const float4*)(B + (size_t)(k0 + r) * N + gc);
            } else {
                v.x = (gc + 0 < N) ? B[(size_t)(k0 + r) * N + gc + 0] : 0.f;
                v.y = (gc + 1 < N) ? B[(size_t)(k0 + r) * N + gc + 1] : 0.f;
                v.z = (gc + 2 < N) ? B[(size_t)(k0 + r) * N + gc + 2] : 0.f;
                v.w = (gc + 3 < N) ? B[(size_t)(k0 + r) * N + gc + 3] : 0.f;
            }
            *(float4*)&Bs[r][bCol] = v;
        }
        __syncthreads();
        #pragma unroll
        for (int kk = 0; kk < BK; ++kk) {
            float ra[TM], rb[TN];
            #pragma unroll
            for (int i = 0; i < TM; ++i) ra[i] = As[kk][trow + i];
            #pragma unroll
            for (int j = 0; j < TN; ++j) rb[j] = Bs[kk][tcol + j];
            #pragma unroll
            for (int i = 0; i < TM; ++i)
                #pragma unroll
                for (int j = 0; j < TN; ++j)
                    acc[i][j] = fmaf(ra[i], rb[j], acc[i][j]);
        }
        __syncthreads();
    }

    #pragma unroll
    for (int i = 0; i < TM; ++i) {
        const int gr = tileRow + trow + i;
        #pragma unroll
        for (int j = 0; j < TN; ++j) {
            const int gc = tileCol + tcol + j;
            if (gc < N) {
                size_t idx = (size_t)gr * N + gc;
                float v = acc[i][j];
                if (Cadd) v += Cadd[idx];
                C[idx] = v;
            }
        }
    }
}

// ---------------- 3) causal depthwise conv (K=4) + SiLU ----------------
__global__ void conv_kernel(const float* __restrict__ conv_w,
                            const float* __restrict__ conv_b) {
    const int c = blockIdx.x * 256 + threadIdx.x;   // 0..1279
    const int l = blockIdx.y;
    const int b = blockIdx.z;
    const size_t colbase = ((size_t)b * LL) * DPROJ + DIN + c;  // row b*LL, channel DIN+c
    const float w0 = conv_w[c * 4 + 0], w1 = conv_w[c * 4 + 1];
    const float w2 = conv_w[c * 4 + 2], w3 = conv_w[c * 4 + 3];
    float acc = conv_b[c];
    if (l >= 3) acc = fmaf(g_zx[colbase + (size_t)(l - 3) * DPROJ], w0, acc);
    if (l >= 2) acc = fmaf(g_zx[colbase + (size_t)(l - 2) * DPROJ], w1, acc);
    if (l >= 1) acc = fmaf(g_zx[colbase + (size_t)(l - 1) * DPROJ], w2, acc);
    acc = fmaf(g_zx[colbase + (size_t)l * DPROJ], w3, acc);
    g_xconv[((size_t)b * LL + l) * DCONVCH + c] = siluf(acc);
}

// ---------------- 4) dt_pos / dA ----------------
__global__ void dt_kernel(const float* __restrict__ dt_bias,
                          const float* __restrict__ A_log) {
    const int i = blockIdx.x * 256 + threadIdx.x;  // 0..ROWS*HH-1
    const int row = i >> 3, h = i & 7;
    float dt = g_zx[(size_t)row * DPROJ + (DPROJ - HH) + h] + dt_bias[h];
    float dtp = (dt > 20.f) ? dt : log1pf(expf(dt));
    g_dtpos[i] = dtp;
    g_dA[i] = expf(-expf(A_log[h]) * dtp);
}

// ---------------- 5) x_shared = mean over heads ----------------
__global__ void xsh_kernel() {
    const int i = blockIdx.x * 256 + threadIdx.x;   // 0..ROWS*PP-1
    const int row = i >> 7, p = i & 127;
    const float* base = g_xconv + (size_t)row * DCONVCH + p;
    float s = 0.f;
    #pragma unroll
    for (int h = 0; h < HH; ++h) s += base[h * PP];
    g_xsh[i] = s * 0.125f;
}

// ---------------- 6) selective scan (n-partitioned, packed f32x2) ----------------
__device__ __forceinline__ void scan_load(int tid, float bsc, int h, int n0,
                                          size_t row0, int tbase,
                                          float* g, float* gx) {
    #pragma unroll
    for (int i = 0; i < SS; ++i) {
        const size_t row = row0 + tbase + i;
        float v = 0.f;
        if (tid < NPN)            v = g_xconv[row * DCONVCH + DIN + n0 + tid] * bsc;
        else if (tid < 2 * NPN)   v = g_xconv[row * DCONVCH + DIN + GN_ + n0 + (tid - NPN)];
        else if (tid == 32)       v = g_dA[row * HH + h];
        else if (tid == 33)       v = g_dtpos[row * HH + h];
        g[i]  = v;
        gx[i] = g_xsh[row * PP + tid];
    }
}

__global__ void __launch_bounds__(128, 1)
scan_kernel(const float* __restrict__ Bscale) {
    const int part = blockIdx.x, h = blockIdx.y, b = blockIdx.z;
    const int tid = threadIdx.x;                 // = p
    const int n0 = part * NPN;
    __shared__ __align__(16) float sh[2][SS][36]; // [0:16)=B*scale, [16:32)=C, 32=dA, 33=dt

    ull state[NPN / 2];
    #pragma unroll
    for (int j = 0; j < NPN / 2; ++j) state[j] = 0ull;

    const float bsc = (tid < NPN) ? Bscale[h * GN_ + n0 + tid] : 0.f;
    const size_t row0 = (size_t)b * LL;

    float g[SS], gx[SS];
    scan_load(tid, bsc, h, n0, row0, 0, g, gx);

    int buf = 0;
    float* yp = g_ypart + ((size_t)part * ROWS + row0) * DIN + (size_t)h * PP + tid;

    for (int t0 = 0; t0 < LL; t0 += SS) {
        if (tid < 34) {
            #pragma unroll
            for (int i = 0; i < SS; ++i) sh[buf][i][tid] = g[i];
        }
        __syncthreads();
        float xpr[SS];
        #pragma unroll
        for (int i = 0; i < SS; ++i) xpr[i] = gx[i];
        if (t0 + SS < LL) scan_load(tid, bsc, h, n0, row0, t0 + SS, g, gx);

        #pragma unroll
        for (int i = 0; i < SS; ++i) {
            const float* s4 = sh[buf][i];
            const ull* s8 = (const ull*)s4;       // pairs: [0:8)=B, [8:16)=C
            const float dA = s4[32];
            const float coef = s4[33] * xpr[i];
            const ull dAp = f32x2_pack(dA, dA);
            const ull cfp = f32x2_pack(coef, coef);
            ull accA = 0ull, accB = 0ull;
            #pragma unroll
            for (int j = 0; j < NPN / 2; ++j) {
                state[j] = f32x2_fma(dAp, state[j], f32x2_mul(cfp, s8[j]));
                if (j & 1) accB = f32x2_fma(s8[8 + j], state[j], accB);
                else       accA = f32x2_fma(s8[8 + j], state[j], accA);
            }
            float2 a = f32x2_unpack(accA);
            float2 c = f32x2_unpack(accB);
            yp[(size_t)(t0 + i) * DIN] = (a.x + a.y) + (c.x + c.y);
        }
        buf ^= 1;
    }
}

// ---------------- 7) combine partials + D*x + gate + RMSNorm ----------------
__global__ void combine_kernel(const float* __restrict__ D_param,
                               const float* __restrict__ rms_w) {
    const int row = blockIdx.x, tid = threadIdx.x;  // 256 threads, 4 channels each
    __shared__ float red[256];
    float yv[4];
    float sq = 0.f;
    #pragma unroll
    for (int q = 0; q < 4; ++q) {
        const int c = q * 256 + tid;
        float s = 0.f;
        #pragma unroll
        for (int part = 0; part < NPART; ++part)
            s += g_ypart[((size_t)part * ROWS + row) * DIN + c];
        s = fmaf(D_param[c >> 7], g_xsh[(size_t)row * PP + (c & 127)], s);
        const float z = g_zx[(size_t)row * DPROJ + c];
        const float yg = s * siluf(z);
        yv[q] = yg;
        sq += yg * yg;
    }
    red[tid] = sq; __syncthreads();
    #pragma unroll
    for (int s2 = 128; s2 > 0; s2 >>= 1) { if (tid < s2) red[tid] += red[tid + s2]; __syncthreads(); }
    const float rstd = rsqrtf(red[0] * (1.f / (float)DIN) + EPS_);
    #pragma unroll
    for (int q = 0; q < 4; ++q) {
        const int c = q * 256 + tid;
        g_yg[(size_t)row * DIN + c] = yv[q] * rstd * rms_w[c];
    }
}

// ---------------- launch ----------------
extern "C" void kernel_launch(void* const* d_in, const int* in_sizes, int n_in,
                              void* d_out, int out_size) {
    const float* u        = (const float*)d_in[0];
    const float* ln_gamma = (const float*)d_in[1];
    const float* ln_beta  = (const float*)d_in[2];
    const float* W_in     = (const float*)d_in[3];
    const float* conv_w   = (const float*)d_in[4];
    const float* conv_b   = (const float*)d_in[5];
    const float* dt_bias  = (const float*)d_in[6];
    const float* A_log    = (const float*)d_in[7];
    const float* D_param  = (const float*)d_in[8];
    const float* B_scale  = (const float*)d_in[9];
    const float* rms_w    = (const float*)d_in[10];
    const float* W_out    = (const float*)d_in[11];
    float* out = (float*)d_out;

    float *p_xn = nullptr, *p_zx = nullptr, *p_yg = nullptr;
    cudaGetSymbolAddress((void**)&p_xn, g_xn);
    cudaGetSymbolAddress((void**)&p_zx, g_zx);
    cudaGetSymbolAddress((void**)&p_yg, g_yg);

    ln_kernel<<<ROWS, 256>>>(u, ln_gamma, ln_beta);

    // zxbcdt = xn @ W_in   [8192 x 2312]
    sgemm_kernel<128, 128, 16, 8, 8><<<dim3((DPROJ + 127) / 128, ROWS / 128), 256>>>(
        ROWS, DPROJ, DM, p_xn, W_in, nullptr, p_zx);

    conv_kernel<<<dim3(DCONVCH / 256, LL, BB), 256>>>(conv_w, conv_b);
    dt_kernel<<<(ROWS * HH) / 256, 256>>>(dt_bias, A_log);
    xsh_kernel<<<(ROWS * PP) / 256, 256>>>();

    scan_kernel<<<dim3(NPART, HH, BB), 128>>>(B_scale);

    combine_kernel<<<ROWS, 256>>>(D_param, rms_w);

    // out = u + yg_normed @ W_out   [8192 x 256]
    sgemm_kernel<128, 128, 16, 8, 8><<<dim3(DM / 128, ROWS / 128), 256>>>(
        ROWS, DM, DIN, p_yg, W_out, u, out);
}

// round 3
// speedup vs baseline: 1.2262x; 1.2262x over previous
#include <cuda_runtime.h>
#include <cuda_bf16.h>
#include <math.h>
#include <stdint.h>

// ---------------- problem constants ----------------
#define BB 2
#define LL 4096
#define DM 256
#define DIN 1024          // D_INNER
#define GN_ 128           // NGROUPS*D_STATE
#define HH 8              // NHEADS
#define PP 128            // HEADDIM
#define DPROJ 2312        // D_IN_PROJ (logical)
#define DPROJP 2432       // padded to 19*128
#define DCONVCH 1280      // D_INNER + 2*GN
#define ROWS (BB*LL)      // 8192
#define EPS_ 1e-5f

#define NPART 8
#define NPN 16            // n per partition
#define SS 4              // scan superstep

// ---------------- scratch (static device allocations) ----------------
__device__ __align__(16) __nv_bfloat16 g_xh[(size_t)ROWS * DM];
__device__ __align__(16) __nv_bfloat16 g_xl[(size_t)ROWS * DM];
__device__ __align__(16) __nv_bfloat16 g_WinT_h[(size_t)DPROJP * DM];
__device__ __align__(16) __nv_bfloat16 g_WinT_l[(size_t)DPROJP * DM];
__device__ __align__(16) __nv_bfloat16 g_WoutT_h[(size_t)DM * DIN];
__device__ __align__(16) __nv_bfloat16 g_WoutT_l[(size_t)DM * DIN];
__device__ __align__(16) __nv_bfloat16 g_yh[(size_t)ROWS * DIN];
__device__ __align__(16) __nv_bfloat16 g_yl[(size_t)ROWS * DIN];
__device__ float g_zx[(size_t)ROWS * DPROJP];
__device__ float g_xconv[(size_t)ROWS * DCONVCH];
__device__ float g_dtpos[(size_t)ROWS * HH];
__device__ float g_dA[(size_t)ROWS * HH];
__device__ float g_xsh[(size_t)ROWS * PP];
__device__ float g_ypart[(size_t)NPART * ROWS * DIN];

// ---------------- small helpers ----------------
__device__ __forceinline__ float siluf(float x) { return x / (1.f + expf(-x)); }

__device__ __forceinline__ void split_bf16(float v, __nv_bfloat16& h, __nv_bfloat16& l) {
    h = __float2bfloat16(v);
    l = __float2bfloat16(v - __bfloat162float(h));
}

typedef unsigned long long ull;
__device__ __forceinline__ ull f32x2_fma(ull a, ull b, ull c) {
    ull d; asm("fma.rn.f32x2 %0, %1, %2, %3;" : "=l"(d) : "l"(a), "l"(b), "l"(c)); return d;
}
__device__ __forceinline__ ull f32x2_mul(ull a, ull b) {
    ull d; asm("mul.rn.f32x2 %0, %1, %2;" : "=l"(d) : "l"(a), "l"(b)); return d;
}
__device__ __forceinline__ ull f32x2_pack(float lo, float hi) {
    ull d; asm("mov.b64 %0, {%1, %2};" : "=l"(d) : "f"(lo), "f"(hi)); return d;
}
__device__ __forceinline__ float2 f32x2_unpack(ull v) {
    float2 r; asm("mov.b64 {%0, %1}, %2;" : "=f"(r.x), "=f"(r.y) : "l"(v)); return r;
}

__device__ __forceinline__ uint32_t smem_u32(const void* p) {
    uint32_t a;
    asm("{ .reg .u64 t; cvta.to.shared.u64 t, %1; cvt.u32.u64 %0, t; }" : "=r"(a) : "l"(p));
    return a;
}

// ---------------- mma.sync helpers ----------------
__device__ __forceinline__ void cp_async16(uint32_t saddr, const void* gptr) {
    asm volatile("cp.async.cg.shared.global [%0], [%1], 16;"
                 :: "r"(saddr), "l"(gptr) : "memory");
}
#define CP_COMMIT() asm volatile("cp.async.commit_group;" ::: "memory")
template <int N> __device__ __forceinline__ void cp_wait() {
    asm volatile("cp.async.wait_group %0;" :: "n"(N) : "memory");
}

__device__ __forceinline__ void ldmatrix_x4(uint32_t* r, uint32_t addr) {
    asm volatile("ldmatrix.sync.aligned.m8n8.x4.shared.b16 {%0,%1,%2,%3}, [%4];"
                 : "=r"(r[0]), "=r"(r[1]), "=r"(r[2]), "=r"(r[3]) : "r"(addr));
}

__device__ __forceinline__ void mma_bf16(float* c, const uint32_t* a, uint32_t b0, uint32_t b1) {
    asm volatile(
        "mma.sync.aligned.m16n8k16.row.col.f32.bf16.bf16.f32 "
        "{%0,%1,%2,%3}, {%4,%5,%6,%7}, {%8,%9}, {%0,%1,%2,%3};"
        : "+f"(c[0]), "+f"(c[1]), "+f"(c[2]), "+f"(c[3])
        : "r"(a[0]), "r"(a[1]), "r"(a[2]), "r"(a[3]), "r"(b0), "r"(b1));
}

// ---------------- 1) LayerNorm -> split bf16 ----------------
__global__ void ln_kernel(const float* __restrict__ u,
                          const float* __restrict__ gamma,
                          const float* __restrict__ beta) {
    __shared__ float red[256];
    const int row = blockIdx.x, tid = threadIdx.x;
    float v = u[(size_t)row * DM + tid];
    red[tid] = v; __syncthreads();
    #pragma unroll
    for (int s = 128; s > 0; s >>= 1) { if (tid < s) red[tid] += red[tid + s]; __syncthreads(); }
    float mu = red[0] * (1.f / 256.f);
    __syncthreads();
    float d = v - mu;
    red[tid] = d * d; __syncthreads();
    #pragma unroll
    for (int s = 128; s > 0; s >>= 1) { if (tid < s) red[tid] += red[tid + s]; __syncthreads(); }
    float var = red[0] * (1.f / 256.f);
    float xn = d * rsqrtf(var + EPS_) * gamma[tid] + beta[tid];
    __nv_bfloat16 h, l;
    split_bf16(xn, h, l);
    g_xh[(size_t)row * DM + tid] = h;
    g_xl[(size_t)row * DM + tid] = l;
}

// ---------------- transposes + split of weights ----------------
__global__ void transpose_win_kernel(const float* __restrict__ W_in) {
    const int n = blockIdx.x;           // 0..2431
    const int k = threadIdx.x;          // 0..255
    float v = (n < DPROJ) ? W_in[(size_t)k * DPROJ + n] : 0.f;
    __nv_bfloat16 h, l;
    split_bf16(v, h, l);
    g_WinT_h[(size_t)n * DM + k] = h;
    g_WinT_l[(size_t)n * DM + k] = l;
}

__global__ void transpose_wout_kernel(const float* __restrict__ W_out) {
    const int n = blockIdx.x;           // 0..255
    for (int k = threadIdx.x; k < DIN; k += 256) {
        float v = W_out[(size_t)k * DM + n];
        __nv_bfloat16 h, l;
        split_bf16(v, h, l);
        g_WoutT_h[(size_t)n * DIN + k] = h;
        g_WoutT_l[(size_t)n * DIN + k] = l;
    }
}

// ---------------- 2) split-bf16 GEMM on mma.sync (HMMA) ----------------
// D[M,N](fp32) = A[M,K] * B[N,K]^T, K-segments (Ah,Bh),(Al,Bh),(Ah,Bl).
// CTA tile 128x128, BK=32, 8 warps (2x4), warp tile 64x32, double-buffered cp.async.
#define STR 40   // smem row stride (bf16): conflict-free for ldmatrix

__global__ void __launch_bounds__(256)
mma_gemm_kernel(const __nv_bfloat16* __restrict__ Ah,
                const __nv_bfloat16* __restrict__ Al,
                const __nv_bfloat16* __restrict__ Bh,
                const __nv_bfloat16* __restrict__ Bl,
                int Kin,
                float* __restrict__ C, int ldc,
                const float* __restrict__ Cadd) {
    __shared__ __align__(16) __nv_bfloat16 As[2][128 * STR];
    __shared__ __align__(16) __nv_bfloat16 Bs[2][128 * STR];

    const int tid = threadIdx.x;
    const int wid = tid >> 5, lid = tid & 31;
    const int wm = wid >> 2;           // 0..1
    const int wn = wid & 3;            // 0..3
    const int tileRow = blockIdx.y * 128;
    const int tileCol = blockIdx.x * 128;

    const uint32_t saBase0 = smem_u32(&As[0][0]);
    const uint32_t saBase1 = smem_u32(&As[1][0]);
    const uint32_t sbBase0 = smem_u32(&Bs[0][0]);
    const uint32_t sbBase1 = smem_u32(&Bs[1][0]);

    // staging mapping: thread -> (row = tid/2, 16-elem segment = (tid&1)*16)
    const int stRow = tid >> 1;
    const int stSeg = (tid & 1) * 16;
    const uint32_t stOffB = (uint32_t)(stRow * STR + stSeg) * 2;

    // ldmatrix lane offsets
    const int aRowOff = (lid & 7) + ((lid >> 3) & 1) * 8;
    const int aKOff   = (lid >> 4) * 8;
    const int bNOff   = (lid & 7) + ((lid >> 4) & 1) * 8;
    const int bKOff   = ((lid >> 3) & 1) * 8;

    float acc[4][4][4];
    #pragma unroll
    for (int i = 0; i < 4; ++i)
        #pragma unroll
        for (int j = 0; j < 4; ++j)
            #pragma unroll
            for (int q = 0; q < 4; ++q) acc[i][j][q] = 0.f;

    const int cps = Kin / 32;
    const int T = 3 * cps;

    auto issue = [&](int c) {
        const int seg = c / cps;
        const int kc = c - seg * cps;
        const __nv_bfloat16* Ag = (seg == 1) ? Al : Ah;
        const __nv_bfloat16* Bg = (seg == 2) ? Bl : Bh;
        const __nv_bfloat16* ga = Ag + (size_t)(tileRow + stRow) * Kin + kc * 32 + stSeg;
        const __nv_bfloat16* gb = Bg + (size_t)(tileCol + stRow) * Kin + kc * 32 + stSeg;
        const uint32_t sa = ((c & 1) ? saBase1 : saBase0) + stOffB;
        const uint32_t sb = ((c & 1) ? sbBase1 : sbBase0) + stOffB;
        cp_async16(sa, ga);
        cp_async16(sa + 16, ga + 8);
        cp_async16(sb, gb);
        cp_async16(sb + 16, gb + 8);
        CP_COMMIT();
    };

    issue(0);
    for (int c = 0; c < T; ++c) {
        if (c + 1 < T) { issue(c + 1); cp_wait<1>(); }
        else           { cp_wait<0>(); }
        __syncthreads();

        const uint32_t aB = (c & 1) ? saBase1 : saBase0;
        const uint32_t bB = (c & 1) ? sbBase1 : sbBase0;
        #pragma unroll
        for (int kk = 0; kk < 32; kk += 16) {
            uint32_t afr[4][4];
            #pragma unroll
            for (int mt = 0; mt < 4; ++mt) {
                uint32_t addr = aB + (uint32_t)((wm * 64 + mt * 16 + aRowOff) * STR + kk + aKOff) * 2;
                ldmatrix_x4(afr[mt], addr);
            }
            uint32_t bfr[2][4];
            #pragma unroll
            for (int pr = 0; pr < 2; ++pr) {
                uint32_t addr = bB + (uint32_t)((wn * 32 + pr * 16 + bNOff) * STR + kk + bKOff) * 2;
                ldmatrix_x4(bfr[pr], addr);
            }
            #pragma unroll
            for (int mt = 0; mt < 4; ++mt)
                #pragma unroll
                for (int nt = 0; nt < 4; ++nt) {
                    const uint32_t* bp = bfr[nt >> 1];
                    const int hi = (nt & 1) * 2;
                    mma_bf16(acc[mt][nt], afr[mt], bp[hi], bp[hi + 1]);
                }
        }
        __syncthreads();
    }

    // epilogue
    const int gID = lid >> 2, qid = lid & 3;
    #pragma unroll
    for (int mt = 0; mt < 4; ++mt) {
        const int r0 = tileRow + wm * 64 + mt * 16 + gID;
        #pragma unroll
        for (int nt = 0; nt < 4; ++nt) {
            const int col = tileCol + wn * 32 + nt * 8 + qid * 2;
            float2 v0 = make_float2(acc[mt][nt][0], acc[mt][nt][1]);
            float2 v1 = make_float2(acc[mt][nt][2], acc[mt][nt][3]);
            if (Cadd) {
                const float2 a0 = *(const float2*)(Cadd + (size_t)r0 * ldc + col);
                const float2 a1 = *(const float2*)(Cadd + (size_t)(r0 + 8) * ldc + col);
                v0.x += a0.x; v0.y += a0.y;
                v1.x += a1.x; v1.y += a1.y;
            }
            *(float2*)(C + (size_t)r0 * ldc + col) = v0;
            *(float2*)(C + (size_t)(r0 + 8) * ldc + col) = v1;
        }
    }
}

// ---------------- 3) causal depthwise conv (K=4) + SiLU ----------------
__global__ void conv_kernel(const float* __restrict__ conv_w,
                            const float* __restrict__ conv_b) {
    const int c = blockIdx.x * 256 + threadIdx.x;   // 0..1279
    const int l = blockIdx.y;
    const int b = blockIdx.z;
    const size_t colbase = ((size_t)b * LL) * DPROJP + DIN + c;
    const float w0 = conv_w[c * 4 + 0], w1 = conv_w[c * 4 + 1];
    const float w2 = conv_w[c * 4 + 2], w3 = conv_w[c * 4 + 3];
    float acc = conv_b[c];
    if (l >= 3) acc = fmaf(g_zx[colbase + (size_t)(l - 3) * DPROJP], w0, acc);
    if (l >= 2) acc = fmaf(g_zx[colbase + (size_t)(l - 2) * DPROJP], w1, acc);
    if (l >= 1) acc = fmaf(g_zx[colbase + (size_t)(l - 1) * DPROJP], w2, acc);
    acc = fmaf(g_zx[colbase + (size_t)l * DPROJP], w3, acc);
    g_xconv[((size_t)b * LL + l) * DCONVCH + c] = siluf(acc);
}

// ---------------- 4) dt_pos / dA ----------------
__global__ void dt_kernel(const float* __restrict__ dt_bias,
                          const float* __restrict__ A_log) {
    const int i = blockIdx.x * 256 + threadIdx.x;  // 0..ROWS*HH-1
    const int row = i >> 3, h = i & 7;
    float dt = g_zx[(size_t)row * DPROJP + 2304 + h] + dt_bias[h];
    float dtp = (dt > 20.f) ? dt : log1pf(expf(dt));
    g_dtpos[i] = dtp;
    g_dA[i] = expf(-expf(A_log[h]) * dtp);
}

// ---------------- 5) x_shared = mean over heads ----------------
__global__ void xsh_kernel() {
    const int i = blockIdx.x * 256 + threadIdx.x;   // 0..ROWS*PP-1
    const int row = i >> 7, p = i & 127;
    const float* base = g_xconv + (size_t)row * DCONVCH + p;
    float s = 0.f;
    #pragma unroll
    for (int h = 0; h < HH; ++h) s += base[h * PP];
    g_xsh[i] = s * 0.125f;
}

// ---------------- 6) selective scan (n-partitioned, packed f32x2) ----------------
__device__ __forceinline__ void scan_load(int tid, float bsc, int h, int n0,
                                          size_t row0, int tbase,
                                          float* g, float* gx) {
    #pragma unroll
    for (int i = 0; i < SS; ++i) {
        const size_t row = row0 + tbase + i;
        float v = 0.f;
        if (tid < NPN)            v = g_xconv[row * DCONVCH + DIN + n0 + tid] * bsc;
        else if (tid < 2 * NPN)   v = g_xconv[row * DCONVCH + DIN + GN_ + n0 + (tid - NPN)];
        else if (tid == 32)       v = g_dA[row * HH + h];
        else if (tid == 33)       v = g_dtpos[row * HH + h];
        g[i]  = v;
        gx[i] = g_xsh[row * PP + tid];
    }
}

__global__ void __launch_bounds__(128, 1)
scan_kernel(const float* __restrict__ Bscale) {
    const int part = blockIdx.x, h = blockIdx.y, b = blockIdx.z;
    const int tid = threadIdx.x;                 // = p
    const int n0 = part * NPN;
    __shared__ __align__(16) float sh[2][SS][36];

    ull state[NPN / 2];
    #pragma unroll
    for (int j = 0; j < NPN / 2; ++j) state[j] = 0ull;

    const float bsc = (tid < NPN) ? Bscale[h * GN_ + n0 + tid] : 0.f;
    const size_t row0 = (size_t)b * LL;

    float g[SS], gx[SS];
    scan_load(tid, bsc, h, n0, row0, 0, g, gx);

    int buf = 0;
    float* yp = g_ypart + ((size_t)part * ROWS + row0) * DIN + (size_t)h * PP + tid;

    for (int t0 = 0; t0 < LL; t0 += SS) {
        if (tid < 34) {
            #pragma unroll
            for (int i = 0; i < SS; ++i) sh[buf][i][tid] = g[i];
        }
        __syncthreads();
        float xpr[SS];
        #pragma unroll
        for (int i = 0; i < SS; ++i) xpr[i] = gx[i];
        if (t0 + SS < LL) scan_load(tid, bsc, h, n0, row0, t0 + SS, g, gx);

        #pragma unroll
        for (int i = 0; i < SS; ++i) {
            const float* s4 = sh[buf][i];
            const ull* s8 = (const ull*)s4;
            const float dA = s4[32];
            const float coef = s4[33] * xpr[i];
            const ull dAp = f32x2_pack(dA, dA);
            const ull cfp = f32x2_pack(coef, coef);
            ull accA = 0ull, accB = 0ull;
            #pragma unroll
            for (int j = 0; j < NPN / 2; ++j) {
                state[j] = f32x2_fma(dAp, state[j], f32x2_mul(cfp, s8[j]));
                if (j & 1) accB = f32x2_fma(s8[8 + j], state[j], accB);
                else       accA = f32x2_fma(s8[8 + j], state[j], accA);
            }
            float2 a = f32x2_unpack(accA);
            float2 c = f32x2_unpack(accB);
            yp[(size_t)(t0 + i) * DIN] = (a.x + a.y) + (c.x + c.y);
        }
        buf ^= 1;
    }
}

// ---------------- 7) combine partials + D*x + gate + RMSNorm -> split bf16 ----------------
__global__ void combine_kernel(const float* __restrict__ D_param,
                               const float* __restrict__ rms_w) {
    const int row = blockIdx.x, tid = threadIdx.x;
    __shared__ float red[256];
    float yv[4];
    float sq = 0.f;
    #pragma unroll
    for (int q = 0; q < 4; ++q) {
        const int c = q * 256 + tid;
        float s = 0.f;
        #pragma unroll
        for (int part = 0; part < NPART; ++part)
            s += g_ypart[((size_t)part * ROWS + row) * DIN + c];
        s = fmaf(D_param[c >> 7], g_xsh[(size_t)row * PP + (c & 127)], s);
        const float z = g_zx[(size_t)row * DPROJP + c];
        const float yg = s * siluf(z);
        yv[q] = yg;
        sq += yg * yg;
    }
    red[tid] = sq; __syncthreads();
    #pragma unroll
    for (int s2 = 128; s2 > 0; s2 >>= 1) { if (tid < s2) red[tid] += red[tid + s2]; __syncthreads(); }
    const float rstd = rsqrtf(red[0] * (1.f / (float)DIN) + EPS_);
    #pragma unroll
    for (int q = 0; q < 4; ++q) {
        const int c = q * 256 + tid;
        float v = yv[q] * rstd * rms_w[c];
        __nv_bfloat16 h, l;
        split_bf16(v, h, l);
        g_yh[(size_t)row * DIN + c] = h;
        g_yl[(size_t)row * DIN + c] = l;
    }
}

// ---------------- launch ----------------
extern "C" void kernel_launch(void* const* d_in, const int* in_sizes, int n_in,
                              void* d_out, int out_size) {
    const float* u        = (const float*)d_in[0];
    const float* ln_gamma = (const float*)d_in[1];
    const float* ln_beta  = (const float*)d_in[2];
    const float* W_in     = (const float*)d_in[3];
    const float* conv_w   = (const float*)d_in[4];
    const float* conv_b   = (const float*)d_in[5];
    const float* dt_bias  = (const float*)d_in[6];
    const float* A_log    = (const float*)d_in[7];
    const float* D_param  = (const float*)d_in[8];
    const float* B_scale  = (const float*)d_in[9];
    const float* rms_w    = (const float*)d_in[10];
    const float* W_out    = (const float*)d_in[11];
    float* out = (float*)d_out;

    __nv_bfloat16 *p_xh, *p_xl, *p_winh, *p_winl, *p_wouth, *p_woutl, *p_yh, *p_yl;
    float* p_zx;
    cudaGetSymbolAddress((void**)&p_xh, g_xh);
    cudaGetSymbolAddress((void**)&p_xl, g_xl);
    cudaGetSymbolAddress((void**)&p_winh, g_WinT_h);
    cudaGetSymbolAddress((void**)&p_winl, g_WinT_l);
    cudaGetSymbolAddress((void**)&p_wouth, g_WoutT_h);
    cudaGetSymbolAddress((void**)&p_woutl, g_WoutT_l);
    cudaGetSymbolAddress((void**)&p_yh, g_yh);
    cudaGetSymbolAddress((void**)&p_yl, g_yl);
    cudaGetSymbolAddress((void**)&p_zx, g_zx);

    ln_kernel<<<ROWS, 256>>>(u, ln_gamma, ln_beta);
    transpose_win_kernel<<<DPROJP, 256>>>(W_in);
    transpose_wout_kernel<<<DM, 256>>>(W_out);

    // GEMM1: zx[8192 x 2432(pad)] = xn @ W_in  (split-bf16 HMMA)
    mma_gemm_kernel<<<dim3(DPROJP / 128, ROWS / 128), 256>>>(
        p_xh, p_xl, p_winh, p_winl, DM, p_zx, DPROJP, nullptr);

    conv_kernel<<<dim3(DCONVCH / 256, LL, BB), 256>>>(conv_w, conv_b);
    dt_kernel<<<(ROWS * HH) / 256, 256>>>(dt_bias, A_log);
    xsh_kernel<<<(ROWS * PP) / 256, 256>>>();

    scan_kernel<<<dim3(NPART, HH, BB), 128>>>(B_scale);

    combine_kernel<<<ROWS, 256>>>(D_param, rms_w);

    // GEMM2: out[8192 x 256] = yg @ W_out + u
    mma_gemm_kernel<<<dim3(DM / 128, ROWS / 128), 256>>>(
        p_yh, p_yl, p_wouth, p_woutl, DIN, out, DM, u);
}

// round 4
// speedup vs baseline: 4.5609x; 3.7194x over previous
#include <cuda_runtime.h>
#include <cuda_bf16.h>
#include <math.h>
#include <stdint.h>

// ---------------- problem constants ----------------
#define BB 2
#define LL 4096
#define DM 256
#define DIN 1024          // D_INNER
#define GN_ 128           // NGROUPS*D_STATE
#define HH 8              // NHEADS
#define PP 128            // HEADDIM
#define DPROJ 2312        // D_IN_PROJ (logical)
#define DPROJP 2432       // padded to 19*128
#define DCONVCH 1280      // D_INNER + 2*GN
#define ROWS (BB*LL)      // 8192
#define EPS_ 1e-5f

#define NPART 8
#define NPN 16            // n per partition
#define SS 8              // scan superstep (timesteps per pipeline stage)
#define DST 4             // pipeline depth (stages)
#define NSUP (LL / SS)    // 512

// ---------------- scratch (static device allocations) ----------------
__device__ __align__(16) __nv_bfloat16 g_xh[(size_t)ROWS * DM];
__device__ __align__(16) __nv_bfloat16 g_xl[(size_t)ROWS * DM];
__device__ __align__(16) __nv_bfloat16 g_WinT_h[(size_t)DPROJP * DM];
__device__ __align__(16) __nv_bfloat16 g_WinT_l[(size_t)DPROJP * DM];
__device__ __align__(16) __nv_bfloat16 g_WoutT_h[(size_t)DM * DIN];
__device__ __align__(16) __nv_bfloat16 g_WoutT_l[(size_t)DM * DIN];
__device__ __align__(16) __nv_bfloat16 g_yh[(size_t)ROWS * DIN];
__device__ __align__(16) __nv_bfloat16 g_yl[(size_t)ROWS * DIN];
__device__ float g_zx[(size_t)ROWS * DPROJP];
__device__ float g_xconv[(size_t)ROWS * DCONVCH];
__device__ float g_dtpos[(size_t)ROWS * HH];
__device__ float g_dA[(size_t)ROWS * HH];
__device__ float g_xsh[(size_t)ROWS * PP];
__device__ float g_ypart[(size_t)NPART * ROWS * DIN];

// ---------------- small helpers ----------------
__device__ __forceinline__ float siluf(float x) { return x / (1.f + expf(-x)); }

__device__ __forceinline__ void split_bf16(float v, __nv_bfloat16& h, __nv_bfloat16& l) {
    h = __float2bfloat16(v);
    l = __float2bfloat16(v - __bfloat162float(h));
}

typedef unsigned long long ull;
__device__ __forceinline__ ull f32x2_fma(ull a, ull b, ull c) {
    ull d; asm("fma.rn.f32x2 %0, %1, %2, %3;" : "=l"(d) : "l"(a), "l"(b), "l"(c)); return d;
}
__device__ __forceinline__ ull f32x2_mul(ull a, ull b) {
    ull d; asm("mul.rn.f32x2 %0, %1, %2;" : "=l"(d) : "l"(a), "l"(b)); return d;
}
__device__ __forceinline__ ull f32x2_pack(float lo, float hi) {
    ull d; asm("mov.b64 %0, {%1, %2};" : "=l"(d) : "f"(lo), "f"(hi)); return d;
}
__device__ __forceinline__ float2 f32x2_unpack(ull v) {
    float2 r; asm("mov.b64 {%0, %1}, %2;" : "=f"(r.x), "=f"(r.y) : "l"(v)); return r;
}

__device__ __forceinline__ uint32_t smem_u32(const void* p) {
    uint32_t a;
    asm("{ .reg .u64 t; cvta.to.shared.u64 t, %1; cvt.u32.u64 %0, t; }" : "=r"(a) : "l"(p));
    return a;
}

// ---------------- async copy helpers ----------------
__device__ __forceinline__ void cp_async16(uint32_t saddr, const void* gptr) {
    asm volatile("cp.async.cg.shared.global [%0], [%1], 16;"
                 :: "r"(saddr), "l"(gptr) : "memory");
}
__device__ __forceinline__ void cp_async4(uint32_t saddr, const void* gptr) {
    asm volatile("cp.async.ca.shared.global [%0], [%1], 4;"
                 :: "r"(saddr), "l"(gptr) : "memory");
}
#define CP_COMMIT() asm volatile("cp.async.commit_group;" ::: "memory")
template <int N> __device__ __forceinline__ void cp_wait() {
    asm volatile("cp.async.wait_group %0;" :: "n"(N) : "memory");
}

__device__ __forceinline__ void ldmatrix_x4(uint32_t* r, uint32_t addr) {
    asm volatile("ldmatrix.sync.aligned.m8n8.x4.shared.b16 {%0,%1,%2,%3}, [%4];"
                 : "=r"(r[0]), "=r"(r[1]), "=r"(r[2]), "=r"(r[3]) : "r"(addr));
}

__device__ __forceinline__ void mma_bf16(float* c, const uint32_t* a, uint32_t b0, uint32_t b1) {
    asm volatile(
        "mma.sync.aligned.m16n8k16.row.col.f32.bf16.bf16.f32 "
        "{%0,%1,%2,%3}, {%4,%5,%6,%7}, {%8,%9}, {%0,%1,%2,%3};"
        : "+f"(c[0]), "+f"(c[1]), "+f"(c[2]), "+f"(c[3])
        : "r"(a[0]), "r"(a[1]), "r"(a[2]), "r"(a[3]), "r"(b0), "r"(b1));
}

// ---------------- 1) LayerNorm -> split bf16 ----------------
__global__ void ln_kernel(const float* __restrict__ u,
                          const float* __restrict__ gamma,
                          const float* __restrict__ beta) {
    __shared__ float red[256];
    const int row = blockIdx.x, tid = threadIdx.x;
    float v = u[(size_t)row * DM + tid];
    red[tid] = v; __syncthreads();
    #pragma unroll
    for (int s = 128; s > 0; s >>= 1) { if (tid < s) red[tid] += red[tid + s]; __syncthreads(); }
    float mu = red[0] * (1.f / 256.f);
    __syncthreads();
    float d = v - mu;
    red[tid] = d * d; __syncthreads();
    #pragma unroll
    for (int s = 128; s > 0; s >>= 1) { if (tid < s) red[tid] += red[tid + s]; __syncthreads(); }
    float var = red[0] * (1.f / 256.f);
    float xn = d * rsqrtf(var + EPS_) * gamma[tid] + beta[tid];
    __nv_bfloat16 h, l;
    split_bf16(xn, h, l);
    g_xh[(size_t)row * DM + tid] = h;
    g_xl[(size_t)row * DM + tid] = l;
}

// ---------------- transposes + split of weights ----------------
__global__ void transpose_win_kernel(const float* __restrict__ W_in) {
    const int n = blockIdx.x;           // 0..2431
    const int k = threadIdx.x;          // 0..255
    float v = (n < DPROJ) ? W_in[(size_t)k * DPROJ + n] : 0.f;
    __nv_bfloat16 h, l;
    split_bf16(v, h, l);
    g_WinT_h[(size_t)n * DM + k] = h;
    g_WinT_l[(size_t)n * DM + k] = l;
}

__global__ void transpose_wout_kernel(const float* __restrict__ W_out) {
    const int n = blockIdx.x;           // 0..255
    for (int k = threadIdx.x; k < DIN; k += 256) {
        float v = W_out[(size_t)k * DM + n];
        __nv_bfloat16 h, l;
        split_bf16(v, h, l);
        g_WoutT_h[(size_t)n * DIN + k] = h;
        g_WoutT_l[(size_t)n * DIN + k] = l;
    }
}

// ---------------- 2) split-bf16 GEMM on mma.sync (HMMA) ----------------
#define STR 40   // smem row stride (bf16): conflict-free for ldmatrix

__global__ void __launch_bounds__(256)
mma_gemm_kernel(const __nv_bfloat16* __restrict__ Ah,
                const __nv_bfloat16* __restrict__ Al,
                const __nv_bfloat16* __restrict__ Bh,
                const __nv_bfloat16* __restrict__ Bl,
                int Kin,
                float* __restrict__ C, int ldc,
                const float* __restrict__ Cadd) {
    __shared__ __align__(16) __nv_bfloat16 As[2][128 * STR];
    __shared__ __align__(16) __nv_bfloat16 Bs[2][128 * STR];

    const int tid = threadIdx.x;
    const int wid = tid >> 5, lid = tid & 31;
    const int wm = wid >> 2;           // 0..1
    const int wn = wid & 3;            // 0..3
    const int tileRow = blockIdx.y * 128;
    const int tileCol = blockIdx.x * 128;

    const uint32_t saBase0 = smem_u32(&As[0][0]);
    const uint32_t saBase1 = smem_u32(&As[1][0]);
    const uint32_t sbBase0 = smem_u32(&Bs[0][0]);
    const uint32_t sbBase1 = smem_u32(&Bs[1][0]);

    const int stRow = tid >> 1;
    const int stSeg = (tid & 1) * 16;
    const uint32_t stOffB = (uint32_t)(stRow * STR + stSeg) * 2;

    const int aRowOff = (lid & 7) + ((lid >> 3) & 1) * 8;
    const int aKOff   = (lid >> 4) * 8;
    const int bNOff   = (lid & 7) + ((lid >> 4) & 1) * 8;
    const int bKOff   = ((lid >> 3) & 1) * 8;

    float acc[4][4][4];
    #pragma unroll
    for (int i = 0; i < 4; ++i)
        #pragma unroll
        for (int j = 0; j < 4; ++j)
            #pragma unroll
            for (int q = 0; q < 4; ++q) acc[i][j][q] = 0.f;

    const int cps = Kin / 32;
    const int T = 3 * cps;

    auto issue = [&](int c) {
        const int seg = c / cps;
        const int kc = c - seg * cps;
        const __nv_bfloat16* Ag = (seg == 1) ? Al : Ah;
        const __nv_bfloat16* Bg = (seg == 2) ? Bl : Bh;
        const __nv_bfloat16* ga = Ag + (size_t)(tileRow + stRow) * Kin + kc * 32 + stSeg;
        const __nv_bfloat16* gb = Bg + (size_t)(tileCol + stRow) * Kin + kc * 32 + stSeg;
        const uint32_t sa = ((c & 1) ? saBase1 : saBase0) + stOffB;
        const uint32_t sb = ((c & 1) ? sbBase1 : sbBase0) + stOffB;
        cp_async16(sa, ga);
        cp_async16(sa + 16, ga + 8);
        cp_async16(sb, gb);
        cp_async16(sb + 16, gb + 8);
        CP_COMMIT();
    };

    issue(0);
    for (int c = 0; c < T; ++c) {
        if (c + 1 < T) { issue(c + 1); cp_wait<1>(); }
        else           { cp_wait<0>(); }
        __syncthreads();

        const uint32_t aB = (c & 1) ? saBase1 : saBase0;
        const uint32_t bB = (c & 1) ? sbBase1 : sbBase0;
        #pragma unroll
        for (int kk = 0; kk < 32; kk += 16) {
            uint32_t afr[4][4];
            #pragma unroll
            for (int mt = 0; mt < 4; ++mt) {
                uint32_t addr = aB + (uint32_t)((wm * 64 + mt * 16 + aRowOff) * STR + kk + aKOff) * 2;
                ldmatrix_x4(afr[mt], addr);
            }
            uint32_t bfr[2][4];
            #pragma unroll
            for (int pr = 0; pr < 2; ++pr) {
                uint32_t addr = bB + (uint32_t)((wn * 32 + pr * 16 + bNOff) * STR + kk + bKOff) * 2;
                ldmatrix_x4(bfr[pr], addr);
            }
            #pragma unroll
            for (int mt = 0; mt < 4; ++mt)
                #pragma unroll
                for (int nt = 0; nt < 4; ++nt) {
                    const uint32_t* bp = bfr[nt >> 1];
                    const int hi = (nt & 1) * 2;
                    mma_bf16(acc[mt][nt], afr[mt], bp[hi], bp[hi + 1]);
                }
        }
        __syncthreads();
    }

    const int gID = lid >> 2, qid = lid & 3;
    #pragma unroll
    for (int mt = 0; mt < 4; ++mt) {
        const int r0 = tileRow + wm * 64 + mt * 16 + gID;
        #pragma unroll
        for (int nt = 0; nt < 4; ++nt) {
            const int col = tileCol + wn * 32 + nt * 8 + qid * 2;
            float2 v0 = make_float2(acc[mt][nt][0], acc[mt][nt][1]);
            float2 v1 = make_float2(acc[mt][nt][2], acc[mt][nt][3]);
            if (Cadd) {
                const float2 a0 = *(const float2*)(Cadd + (size_t)r0 * ldc + col);
                const float2 a1 = *(const float2*)(Cadd + (size_t)(r0 + 8) * ldc + col);
                v0.x += a0.x; v0.y += a0.y;
                v1.x += a1.x; v1.y += a1.y;
            }
            *(float2*)(C + (size_t)r0 * ldc + col) = v0;
            *(float2*)(C + (size_t)(r0 + 8) * ldc + col) = v1;
        }
    }
}

// ---------------- 3) causal depthwise conv (K=4) + SiLU ----------------
__global__ void conv_kernel(const float* __restrict__ conv_w,
                            const float* __restrict__ conv_b) {
    const int c = blockIdx.x * 256 + threadIdx.x;   // 0..1279
    const int l = blockIdx.y;
    const int b = blockIdx.z;
    const size_t colbase = ((size_t)b * LL) * DPROJP + DIN + c;
    const float w0 = conv_w[c * 4 + 0], w1 = conv_w[c * 4 + 1];
    const float w2 = conv_w[c * 4 + 2], w3 = conv_w[c * 4 + 3];
    float acc = conv_b[c];
    if (l >= 3) acc = fmaf(g_zx[colbase + (size_t)(l - 3) * DPROJP], w0, acc);
    if (l >= 2) acc = fmaf(g_zx[colbase + (size_t)(l - 2) * DPROJP], w1, acc);
    if (l >= 1) acc = fmaf(g_zx[colbase + (size_t)(l - 1) * DPROJP], w2, acc);
    acc = fmaf(g_zx[colbase + (size_t)l * DPROJP], w3, acc);
    g_xconv[((size_t)b * LL + l) * DCONVCH + c] = siluf(acc);
}

// ---------------- 4) dt_pos / dA ----------------
__global__ void dt_kernel(const float* __restrict__ dt_bias,
                          const float* __restrict__ A_log) {
    const int i = blockIdx.x * 256 + threadIdx.x;  // 0..ROWS*HH-1
    const int row = i >> 3, h = i & 7;
    float dt = g_zx[(size_t)row * DPROJP + 2304 + h] + dt_bias[h];
    float dtp = (dt > 20.f) ? dt : log1pf(expf(dt));
    g_dtpos[i] = dtp;
    g_dA[i] = expf(-expf(A_log[h]) * dtp);
}

// ---------------- 5) x_shared = mean over heads ----------------
__global__ void xsh_kernel() {
    const int i = blockIdx.x * 256 + threadIdx.x;   // 0..ROWS*PP-1
    const int row = i >> 7, p = i & 127;
    const float* base = g_xconv + (size_t)row * DCONVCH + p;
    float s = 0.f;
    #pragma unroll
    for (int h = 0; h < HH; ++h) s += base[h * PP];
    g_xsh[i] = s * 0.125f;
}

// ---------------- 6) selective scan: cp.async multistage pipeline ----------------
// Ring slot layout per timestep (168 floats, 672B, 16B-aligned):
//   [0:16)  B_shared (raw, 16 n-vals)   [16:32) C_shared   [32:160) xsh (128)
//   [160] dA   [161] dt   [162:168) pad
#define SLOTF 168

__global__ void __launch_bounds__(128, 1)
scan_kernel(const float* __restrict__ Bscale) {
    __shared__ __align__(16) float ring[DST][SS][SLOTF];

    const int part = blockIdx.x, h = blockIdx.y, b = blockIdx.z;
    const int tid = threadIdx.x;                 // = p
    const int n0 = part * NPN;
    const int lane16 = tid & 15;
    const int tgrp = tid >> 4;                   // timestep-in-superstep this thread stages
    const size_t row0 = (size_t)b * LL;

    // per-thread copies of head-scale pairs (uniform across threads)
    ull bscp[8];
    #pragma unroll
    for (int j = 0; j < 8; ++j) {
        float2 bs = *(const float2*)(Bscale + h * GN_ + n0 + 2 * j);
        bscp[j] = f32x2_pack(bs.x, bs.y);
    }

    ull state[8];
    #pragma unroll
    for (int j = 0; j < 8; ++j) state[j] = 0ull;

    // producer: stage superstep s into ring[s % DST]
    auto issue = [&](int s) {
        if (s < NSUP) {
            const size_t row = row0 + (size_t)s * SS + tgrp;
            float* dstT = &ring[s & (DST - 1)][tgrp][0];
            const float* convrow = g_xconv + row * DCONVCH;
            const float* xshrow  = g_xsh + row * PP;
            #pragma unroll
            for (int c = lane16; c < 40; c += 16) {
                const float* src;
                float* dst;
                if (c < 4)      { src = convrow + DIN + n0 + c * 4;             dst = dstT + c * 4; }
                else if (c < 8) { src = convrow + DIN + GN_ + n0 + (c - 4) * 4; dst = dstT + 16 + (c - 4) * 4; }
                else            { src = xshrow + (c - 8) * 4;                   dst = dstT + 32 + (c - 8) * 4; }
                cp_async16(smem_u32(dst), src);
            }
            if (lane16 == 8) cp_async4(smem_u32(dstT + 160), g_dA + row * HH + h);
            if (lane16 == 9) cp_async4(smem_u32(dstT + 161), g_dtpos + row * HH + h);
        }
        CP_COMMIT();
    };

    // prologue: stages 0 .. DST-2 in flight
    #pragma unroll
    for (int s = 0; s < DST - 1; ++s) issue(s);

    float* yp = g_ypart + ((size_t)part * ROWS + row0) * DIN + (size_t)h * PP + tid;

    for (int s = 0; s < NSUP; ++s) {
        cp_wait<DST - 2>();        // stage s landed
        __syncthreads();           // visible to all warps; slot (s-1)%DST free for refill

        const float* slotp = &ring[s & (DST - 1)][0][0];
        #pragma unroll
        for (int i = 0; i < SS; ++i) {
            const float* s4 = slotp + i * SLOTF;
            const ull* s8 = (const ull*)s4;       // [0:8)=B pairs, [8:16)=C pairs
            const float x = s4[32 + tid];
            const float dAv = s4[160];
            const float coef = s4[161] * x;
            const ull dAp = f32x2_pack(dAv, dAv);
            const ull cfp = f32x2_pack(coef, coef);
            ull accA = 0ull, accB = 0ull;
            #pragma unroll
            for (int j = 0; j < 8; ++j) {
                const ull bj = f32x2_mul(bscp[j], s8[j]);
                state[j] = f32x2_fma(dAp, state[j], f32x2_mul(cfp, bj));
                if (j & 1) accB = f32x2_fma(s8[8 + j], state[j], accB);
                else       accA = f32x2_fma(s8[8 + j], state[j], accA);
            }
            float2 a = f32x2_unpack(accA);
            float2 c = f32x2_unpack(accB);
            yp[(size_t)(s * SS + i) * DIN] = (a.x + a.y) + (c.x + c.y);
        }

        issue(s + DST - 1);        // refill slot (s-1)%DST (all warps past barrier)
    }
}

// ---------------- 7) combine partials + D*x + gate + RMSNorm -> split bf16 ----------------
__global__ void combine_kernel(const float* __restrict__ D_param,
                               const float* __restrict__ rms_w) {
    const int row = blockIdx.x, tid = threadIdx.x;
    __shared__ float red[256];
    float yv[4];
    float sq = 0.f;
    #pragma unroll
    for (int q = 0; q < 4; ++q) {
        const int c = q * 256 + tid;
        float s = 0.f;
        #pragma unroll
        for (int part = 0; part < NPART; ++part)
            s += g_ypart[((size_t)part * ROWS + row) * DIN + c];
        s = fmaf(D_param[c >> 7], g_xsh[(size_t)row * PP + (c & 127)], s);
        const float z = g_zx[(size_t)row * DPROJP + c];
        const float yg = s * siluf(z);
        yv[q] = yg;
        sq += yg * yg;
    }
    red[tid] = sq; __syncthreads();
    #pragma unroll
    for (int s2 = 128; s2 > 0; s2 >>= 1) { if (tid < s2) red[tid] += red[tid + s2]; __syncthreads(); }
    const float rstd = rsqrtf(red[0] * (1.f / (float)DIN) + EPS_);
    #pragma unroll
    for (int q = 0; q < 4; ++q) {
        const int c = q * 256 + tid;
        float v = yv[q] * rstd * rms_w[c];
        __nv_bfloat16 h, l;
        split_bf16(v, h, l);
        g_yh[(size_t)row * DIN + c] = h;
        g_yl[(size_t)row * DIN + c] = l;
    }
}

// ---------------- launch ----------------
extern "C" void kernel_launch(void* const* d_in, const int* in_sizes, int n_in,
                              void* d_out, int out_size) {
    const float* u        = (const float*)d_in[0];
    const float* ln_gamma = (const float*)d_in[1];
    const float* ln_beta  = (const float*)d_in[2];
    const float* W_in     = (const float*)d_in[3];
    const float* conv_w   = (const float*)d_in[4];
    const float* conv_b   = (const float*)d_in[5];
    const float* dt_bias  = (const float*)d_in[6];
    const float* A_log    = (const float*)d_in[7];
    const float* D_param  = (const float*)d_in[8];
    const float* B_scale  = (const float*)d_in[9];
    const float* rms_w    = (const float*)d_in[10];
    const float* W_out    = (const float*)d_in[11];
    float* out = (float*)d_out;

    __nv_bfloat16 *p_xh, *p_xl, *p_winh, *p_winl, *p_wouth, *p_woutl, *p_yh, *p_yl;
    float* p_zx;
    cudaGetSymbolAddress((void**)&p_xh, g_xh);
    cudaGetSymbolAddress((void**)&p_xl, g_xl);
    cudaGetSymbolAddress((void**)&p_winh, g_WinT_h);
    cudaGetSymbolAddress((void**)&p_winl, g_WinT_l);
    cudaGetSymbolAddress((void**)&p_wouth, g_WoutT_h);
    cudaGetSymbolAddress((void**)&p_woutl, g_WoutT_l);
    cudaGetSymbolAddress((void**)&p_yh, g_yh);
    cudaGetSymbolAddress((void**)&p_yl, g_yl);
    cudaGetSymbolAddress((void**)&p_zx, g_zx);

    ln_kernel<<<ROWS, 256>>>(u, ln_gamma, ln_beta);
    transpose_win_kernel<<<DPROJP, 256>>>(W_in);
    transpose_wout_kernel<<<DM, 256>>>(W_out);

    // GEMM1: zx[8192 x 2432(pad)] = xn @ W_in  (split-bf16 HMMA)
    mma_gemm_kernel<<<dim3(DPROJP / 128, ROWS / 128), 256>>>(
        p_xh, p_xl, p_winh, p_winl, DM, p_zx, DPROJP, nullptr);

    conv_kernel<<<dim3(DCONVCH / 256, LL, BB), 256>>>(conv_w, conv_b);
    dt_kernel<<<(ROWS * HH) / 256, 256>>>(dt_bias, A_log);
    xsh_kernel<<<(ROWS * PP) / 256, 256>>>();

    scan_kernel<<<dim3(NPART, HH, BB), 128>>>(B_scale);

    combine_kernel<<<ROWS, 256>>>(D_param, rms_w);

    // GEMM2: out[8192 x 256] = yg @ W_out + u
    mma_gemm_kernel<<<dim3(DM / 128, ROWS / 128), 256>>>(
        p_yh, p_yl, p_wouth, p_woutl, DIN, out, DM, u);
}